// round 12
// baseline (speedup 1.0000x reference)
#include <cuda_runtime.h>
#include <math_constants.h>
#include <cstdint>

#define CCH 256
#define HW  65536     // 256*256 pixels

// ---------------- scratch (no allocations allowed) ----------------
__device__ float g_X[CCH * 256];       // X[c][n]
__device__ float g_pH[256 * CCH];      // proto hi plane [slot][c], tf32-exact f32 bits
__device__ float g_pL[256 * CCH];      // proto lo plane [slot][c]
__device__ float g_mlo[CCH], g_mdi[CCH], g_mhi[CCH];
__device__ float g_sel[256];
__device__ int   g_slot[256];
__device__ int   g_selidx[256];
__device__ int   g_S;

// ---------------- helpers ----------------
__device__ __forceinline__ float warp_sum(float v) {
#pragma unroll
    for (int o = 16; o; o >>= 1) v += __shfl_xor_sync(0xffffffffu, v, o);
    return v;
}
__device__ __forceinline__ float warp_max(float v) {
#pragma unroll
    for (int o = 16; o; o >>= 1) v = fmaxf(v, __shfl_xor_sync(0xffffffffu, v, o));
    return v;
}
__device__ __forceinline__ float blk_sum256(float v, float* s, int t) {
    v = warp_sum(v);
    __syncthreads();
    if ((t & 31) == 0) s[t >> 5] = v;
    __syncthreads();
    if (t < 32) {
        float x = (t < 8) ? s[t] : 0.f;
        x = warp_sum(x);
        if (t == 0) s[32] = x;
    }
    __syncthreads();
    float r = s[32];
    __syncthreads();
    return r;
}

// exp(x) for x <= 0 on the FMA pipe (no MUFU)
__device__ __forceinline__ float fast_exp_neg(float x) {
    x = fmaxf(x, -87.f);
    float t = x * 1.44269504088896340736f;
    float n = rintf(t);
    float r = t - n;
    float p = 1.540353039338161e-4f;
    p = fmaf(p, r, 1.3333558146428443e-3f);
    p = fmaf(p, r, 9.618129107628477e-3f);
    p = fmaf(p, r, 5.550410866482158e-2f);
    p = fmaf(p, r, 2.402265069591007e-1f);
    p = fmaf(p, r, 6.931471805599453e-1f);
    p = fmaf(p, r, 1.0f);
    float s = __int_as_float(((int)n + 127) << 23);
    return p * s;
}

__device__ __forceinline__ uint32_t f2tf32(float v) {
    uint32_t r;
    asm("cvt.rna.tf32.f32 %0, %1;" : "=r"(r) : "f"(v));
    return r;
}

#define MMA_TF32(d, a, b0, b1) \
    asm("mma.sync.aligned.m16n8k8.row.col.f32.tf32.tf32.f32 " \
        "{%0,%1,%2,%3}, {%4,%5,%6,%7}, {%8,%9}, {%0,%1,%2,%3};" \
        : "+f"((d)[0]), "+f"((d)[1]), "+f"((d)[2]), "+f"((d)[3]) \
        : "r"((a)[0]), "r"((a)[1]), "r"((a)[2]), "r"((a)[3]), "r"(b0), "r"(b1))

// ---------------- K1a: pool sup_x -> g_X[c][n] ----------------
__global__ void pool_x_kernel(const float* __restrict__ sx) {
    int c = blockIdx.x, t = threadIdx.x;
    const float* base = sx + (size_t)c * HW + t;
    __shared__ float sm[16 * 256];
#pragma unroll
    for (int bh = 0; bh < 16; bh++) {
        float a = 0.f;
#pragma unroll
        for (int r = 0; r < 16; r++) a += base[(bh * 16 + r) * 256];
        sm[bh * 256 + t] = a;
    }
    __syncthreads();
    int bh = t >> 4, bw = t & 15;
    float s = 0.f;
#pragma unroll
    for (int k = 0; k < 16; k++) s += sm[bh * 256 + bw * 16 + k];
    g_X[c * 256 + t] = s * (1.f / 256.f);
}

// ---------------- K1b: pool sup_y -> sel + compaction maps (fused) ----------------
__global__ void pool_y_sel_kernel(const float* __restrict__ sy) {
    int t = threadIdx.x;
    const float* base = sy + t;
    __shared__ float sm[16 * 256];
    __shared__ int ps[256];
#pragma unroll
    for (int bh = 0; bh < 16; bh++) {
        float a = 0.f;
#pragma unroll
        for (int r = 0; r < 16; r++) a += base[(bh * 16 + r) * 256];
        sm[bh * 256 + t] = a;
    }
    __syncthreads();
    int bh = t >> 4, bw = t & 15;
    float s = 0.f;
#pragma unroll
    for (int k = 0; k < 16; k++) s += sm[bh * 256 + bw * 16 + k];
    int sel = ((s * (1.f / 256.f)) > 0.5f) ? 1 : 0;
    g_sel[t] = (float)sel;
    ps[t] = sel;
    g_selidx[t] = 0;
    __syncthreads();
    if (t == 0) {
        int acc = 0;
        for (int n = 0; n < 256; n++) { int v = ps[n]; ps[n] = acc; acc += v; }
        g_S = acc;
    }
    __syncthreads();
    g_slot[t] = ps[t];
    if (sel) g_selidx[ps[t]] = t;
}

// ---------------- K2: w1 rows + softmax -> tridiagonal band (measured 19us) ----------------
#define BK_ROWS 4
__global__ __launch_bounds__(256) void band_kernel(const float* __restrict__ cal) {
    int t = threadIdx.x;
    int i0 = blockIdx.x * BK_ROWS;
    __shared__ float tile[256 * 33];
    __shared__ float wrow[BK_ROWS][256];
    float acc[BK_ROWS] = {0.f, 0.f, 0.f, 0.f};

    for (int k0 = 0; k0 < 256; k0 += 32) {
        __syncthreads();
#pragma unroll
        for (int it = 0; it < 32; it++) {
            int idx = t + it * 256;
            int r = idx >> 5, kk = idx & 31;
            tile[r * 33 + kk] = g_X[r * 256 + k0 + kk];
        }
        __syncthreads();
        float own[32];
#pragma unroll
        for (int kk = 0; kk < 32; kk++) own[kk] = tile[t * 33 + kk];
#pragma unroll
        for (int i = 0; i < BK_ROWS; i++) {
            const float* xi = &tile[(i0 + i) * 33];
            float a = acc[i];
#pragma unroll
            for (int kk = 0; kk < 32; kk++) a = fmaf(own[kk], xi[kk], a);
            acc[i] = a;
        }
    }
#pragma unroll
    for (int i = 0; i < BK_ROWS; i++) wrow[i][t] = acc[i];
    __syncthreads();

    int w = t >> 5, lane = t & 31;
    if (w < BK_ROWS) {
        int i = i0 + w;
        float mx = -CUDART_INF_F;
#pragma unroll
        for (int k = 0; k < 8; k++) mx = fmaxf(mx, wrow[w][k * 32 + lane]);
        mx = warp_max(mx);
        float s = 0.f;
#pragma unroll
        for (int k = 0; k < 8; k++) s += expf(wrow[w][k * 32 + lane] - mx);
        s = warp_sum(s);
        if (lane == 0) {
            float inv = 1.f / s;
            if (i > 0) {
                float e = expf(wrow[w][i - 1] - mx) * inv;
                g_mlo[i] = cal[i * 256 + (i - 1)] * (1.f + 0.2f * e);
            } else g_mlo[0] = 0.f;
            {
                float e = expf(wrow[w][i] - mx) * inv;
                g_mdi[i] = cal[i * 256 + i] * (1.f + 0.2f * e);
            }
            if (i < 255) {
                float e = expf(wrow[w][i + 1] - mx) * inv;
                g_mhi[i] = cal[i * 256 + (i + 1)] * (1.f + 0.2f * e);
            } else g_mhi[255] = 0.f;
        }
    }
}

// ---------------- K3: tridiag apply + col-normalize -> split tf32 planes [slot][c] ----------------
__global__ void proto_kernel() {
    int n = blockIdx.x, i = threadIdx.x;
    __shared__ float sred[40];
    float x0 = g_X[i * 256 + n];
    float xm = (i > 0)   ? g_X[(i - 1) * 256 + n] : 0.f;
    float xp = (i < 255) ? g_X[(i + 1) * 256 + n] : 0.f;
    float v = g_mlo[i] * xm + g_mdi[i] * x0 + g_mhi[i] * xp;
    float ss = blk_sum256(v * v, sred, i);
    float nrm = fmaxf(sqrtf(ss), 1e-4f);
    if (g_sel[n] > 0.f) {
        float pv = v / nrm;
        uint32_t h = f2tf32(pv);
        uint32_t l = f2tf32(pv - __uint_as_float(h));
        int s = g_slot[n];
        g_pH[s * 256 + i] = __uint_as_float(h);   // coalesced row write
        g_pL[s * 256 + i] = __uint_as_float(l);
    }
}

// ---------------- K4: tf32 mma.sync dist + fused softmax/argmax ----------------
// 16 px per CTA (4096 CTAs). A = q split planes [c][px] (pitch 17 f32),
// B = proto split planes [slot][k-chunk16] (pitch 18 f32), staged per chunk.
// Warp w owns n-range [32w, 32w+32); only warps with nq < ceil(S/32) issue mma.
// D[px][slot] = qh*ph + qh*pl + ql*ph (tf32 3-term, err ~1e-5).
#define P_TILE 16
#define OFF_AH 0
#define OFF_AL 4352
#define OFF_BH 8704
#define OFF_BL 13312
#define OFF_PART 17920
#define OFF_NRM  18176
#define OFF_SIDX 18192
#define OFF_SS   18448
#define DIST_SMEM ((18449) * 4)

__global__ __launch_bounds__(256) void dist_kernel(const float* __restrict__ qry,
                                                   float* __restrict__ out) {
    extern __shared__ float dsm[];
    uint32_t* asmH = (uint32_t*)(dsm + OFF_AH);
    uint32_t* asmL = (uint32_t*)(dsm + OFF_AL);
    uint32_t* bsmH = (uint32_t*)(dsm + OFF_BH);
    uint32_t* bsmL = (uint32_t*)(dsm + OFF_BL);
    float* partial = dsm + OFF_PART;
    float* nrm     = dsm + OFF_NRM;
    int*   sidx    = (int*)(dsm + OFF_SIDX);
    int*   sSp     = (int*)(dsm + OFF_SS);

    int t = threadIdx.x;
    int warp = t >> 5, lane = t & 31;
    int g = lane >> 2, qd = lane & 3;
    int p0 = blockIdx.x * P_TILE;

    if (t == 0) *sSp = g_S;
    sidx[t] = g_selidx[t];

    // ---- stage A: load q (coalesced), split to tf32 hi/lo, sumsq ----
    {
        int px = t & 15, cg = t >> 4;
        float ss = 0.f;
#pragma unroll
        for (int r = 0; r < 16; r++) {
            int c = r * 16 + cg;
            float v = qry[(size_t)c * HW + p0 + px];
            ss += v * v;
            uint32_t h = f2tf32(v);
            uint32_t l = f2tf32(v - __uint_as_float(h));
            asmH[c * 17 + px] = h;
            asmL[c * 17 + px] = l;
        }
        partial[t] = ss;
    }
    __syncthreads();
    if (t < 16) {
        float s = 0.f;
#pragma unroll
        for (int j = 0; j < 16; j++) s += partial[t + 16 * j];
        nrm[t] = fmaxf(sqrtf(s), 1e-4f);
    }
    int S = *sSp;
    int nqmax = (S + 31) >> 5;
    bool active = (warp < nqmax);
    int n0w = warp * 32;

    float acc[4][4];
#pragma unroll
    for (int j = 0; j < 4; j++)
#pragma unroll
        for (int m = 0; m < 4; m++) acc[j][m] = 0.f;

    // ---- mainloop: 16 k-chunks of 16 ----
    for (int ch = 0; ch < 16; ch++) {
        int k0 = ch * 16;
        // stage B chunk (both planes), float2 copies
#pragma unroll
        for (int i = 0; i < 8; i++) {
            int id = t + 256 * i;
            int slot = id >> 3, sg = id & 7;
            *(float2*)((float*)bsmH + slot * 18 + sg * 2) =
                *(const float2*)(g_pH + slot * 256 + k0 + sg * 2);
            *(float2*)((float*)bsmL + slot * 18 + sg * 2) =
                *(const float2*)(g_pL + slot * 256 + k0 + sg * 2);
        }
        __syncthreads();
        if (active) {
#pragma unroll
            for (int ks = 0; ks < 2; ks++) {
                int cb = k0 + ks * 8;
                uint32_t ah[4], al[4];
                ah[0] = asmH[(cb + qd) * 17 + g];
                ah[1] = asmH[(cb + qd) * 17 + g + 8];
                ah[2] = asmH[(cb + qd + 4) * 17 + g];
                ah[3] = asmH[(cb + qd + 4) * 17 + g + 8];
                al[0] = asmL[(cb + qd) * 17 + g];
                al[1] = asmL[(cb + qd) * 17 + g + 8];
                al[2] = asmL[(cb + qd + 4) * 17 + g];
                al[3] = asmL[(cb + qd + 4) * 17 + g + 8];
                int kl = ks * 8 + qd;
#pragma unroll
                for (int j = 0; j < 4; j++) {
                    int nb = n0w + j * 8;
                    uint32_t bh0 = bsmH[(nb + g) * 18 + kl];
                    uint32_t bh1 = bsmH[(nb + g) * 18 + kl + 4];
                    uint32_t bl0 = bsmL[(nb + g) * 18 + kl];
                    uint32_t bl1 = bsmL[(nb + g) * 18 + kl + 4];
                    MMA_TF32(acc[j], ah, bh0, bh1);
                    MMA_TF32(acc[j], ah, bl0, bl1);
                    MMA_TF32(acc[j], al, bh0, bh1);
                }
            }
        }
        __syncthreads();
    }

    // ---- d-matrix in smem (reuse A region): [px][slot], pitch 264 ----
    float* dbuf = dsm + OFF_AH;
    const float NEG = -1e9f;
#pragma unroll
    for (int i = 0; i < 17; i++) {
        int idx = t + 256 * i;
        if (idx < 16 * 264) dbuf[idx] = NEG;
    }
    __syncthreads();
    if (active) {
        float sc0 = 20.f / nrm[g];
        float sc1 = 20.f / nrm[g + 8];
#pragma unroll
        for (int j = 0; j < 4; j++) {
            int n = n0w + j * 8 + 2 * qd;
            float d0 = (n     < S) ? acc[j][0] * sc0 : NEG;
            float d1 = (n + 1 < S) ? acc[j][1] * sc0 : NEG;
            float d2 = (n     < S) ? acc[j][2] * sc1 : NEG;
            float d3 = (n + 1 < S) ? acc[j][3] * sc1 : NEG;
            *(float2*)(dbuf + g * 264 + n)       = make_float2(d0, d1);
            *(float2*)(dbuf + (g + 8) * 264 + n) = make_float2(d2, d3);
        }
    }
    __syncthreads();

    // ---- per-pixel softmax-weighted sum + first-tie argmax ----
    int kmax = (S + 31) >> 5;
    for (int pix = warp; pix < P_TILE; pix += 8) {
        if (S == 0) {
            if (lane == 0) { out[p0 + pix] = NEG; out[HW + p0 + pix] = 0.f; }
            continue;
        }
        const float* dp = dbuf + pix * 264;
        float bm = -CUDART_INF_F; int bi = 0;
        for (int k = 0; k < kmax; k++) {
            int n = k * 32 + lane;
            float v2 = (n < S) ? dp[n] : -CUDART_INF_F;
            if (v2 > bm) { bm = v2; bi = n; }
        }
#pragma unroll
        for (int o = 16; o; o >>= 1) {
            float om = __shfl_xor_sync(0xffffffffu, bm, o);
            int   oi = __shfl_xor_sync(0xffffffffu, bi, o);
            if (om > bm || (om == bm && oi < bi)) { bm = om; bi = oi; }
        }
        float se = 0.f, sd = 0.f;
        for (int k = 0; k < kmax; k++) {
            int n = k * 32 + lane;
            if (n < S) {
                float v2 = dp[n];
                float e = fast_exp_neg(v2 - bm);
                se += e; sd += e * v2;
            }
        }
        se = warp_sum(se); sd = warp_sum(sd);
        if (lane == 0) {
            out[p0 + pix]      = sd / se;
            out[HW + p0 + pix] = (float)sidx[bi];
        }
    }
}

// ---------------- launcher ----------------
extern "C" void kernel_launch(void* const* d_in, const int* in_sizes, int n_in,
                              void* d_out, int out_size) {
    const float* qry   = (const float*)d_in[0];
    const float* sup_x = (const float*)d_in[1];
    const float* sup_y = (const float*)d_in[2];
    const float* cal   = (const float*)d_in[4];
    float* out = (float*)d_out;

    cudaFuncSetAttribute(dist_kernel, cudaFuncAttributeMaxDynamicSharedMemorySize, DIST_SMEM);

    pool_x_kernel<<<256, 256>>>(sup_x);
    pool_y_sel_kernel<<<1, 256>>>(sup_y);
    band_kernel<<<64, 256>>>(cal);
    proto_kernel<<<256, 256>>>();
    dist_kernel<<<HW / P_TILE, 256, DIST_SMEM>>>(qry, out);
}

// round 13
// speedup vs baseline: 3.0209x; 3.0209x over previous
#include <cuda_runtime.h>
#include <math_constants.h>
#include <cstdint>

#define CCH 256
#define HW  65536     // 256*256 pixels

// ---------------- scratch (no allocations allowed) ----------------
__device__ float g_X[CCH * 256];       // X[c][n]
__device__ float g_pH[256 * CCH];      // proto hi plane [slot][c], tf32-exact f32 bits
__device__ float g_pL[256 * CCH];      // proto lo plane [slot][c]
__device__ float g_mlo[CCH], g_mdi[CCH], g_mhi[CCH];
__device__ float g_sel[256];
__device__ int   g_slot[256];
__device__ int   g_selidx[256];
__device__ int   g_S;

// ---------------- helpers ----------------
__device__ __forceinline__ float warp_sum(float v) {
#pragma unroll
    for (int o = 16; o; o >>= 1) v += __shfl_xor_sync(0xffffffffu, v, o);
    return v;
}
__device__ __forceinline__ float warp_max(float v) {
#pragma unroll
    for (int o = 16; o; o >>= 1) v = fmaxf(v, __shfl_xor_sync(0xffffffffu, v, o));
    return v;
}
__device__ __forceinline__ float blk_sum256(float v, float* s, int t) {
    v = warp_sum(v);
    __syncthreads();
    if ((t & 31) == 0) s[t >> 5] = v;
    __syncthreads();
    if (t < 32) {
        float x = (t < 8) ? s[t] : 0.f;
        x = warp_sum(x);
        if (t == 0) s[32] = x;
    }
    __syncthreads();
    float r = s[32];
    __syncthreads();
    return r;
}

// exp(x) for x <= 0 on the FMA pipe (no MUFU)
__device__ __forceinline__ float fast_exp_neg(float x) {
    x = fmaxf(x, -87.f);
    float t = x * 1.44269504088896340736f;
    float n = rintf(t);
    float r = t - n;
    float p = 1.540353039338161e-4f;
    p = fmaf(p, r, 1.3333558146428443e-3f);
    p = fmaf(p, r, 9.618129107628477e-3f);
    p = fmaf(p, r, 5.550410866482158e-2f);
    p = fmaf(p, r, 2.402265069591007e-1f);
    p = fmaf(p, r, 6.931471805599453e-1f);
    p = fmaf(p, r, 1.0f);
    float s = __int_as_float(((int)n + 127) << 23);
    return p * s;
}

__device__ __forceinline__ uint32_t f2tf32(float v) {
    uint32_t r;
    asm("cvt.rna.tf32.f32 %0, %1;" : "=r"(r) : "f"(v));
    return r;
}

#define MMA_TF32(d, a, b0, b1) \
    asm("mma.sync.aligned.m16n8k8.row.col.f32.tf32.tf32.f32 " \
        "{%0,%1,%2,%3}, {%4,%5,%6,%7}, {%8,%9}, {%0,%1,%2,%3};" \
        : "+f"((d)[0]), "+f"((d)[1]), "+f"((d)[2]), "+f"((d)[3]) \
        : "r"((a)[0]), "r"((a)[1]), "r"((a)[2]), "r"((a)[3]), "r"(b0), "r"(b1))

// ---------------- K1a: pool sup_x -> g_X[c][n] ----------------
__global__ void pool_x_kernel(const float* __restrict__ sx) {
    int c = blockIdx.x, t = threadIdx.x;
    const float* base = sx + (size_t)c * HW + t;
    __shared__ float sm[16 * 256];
#pragma unroll
    for (int bh = 0; bh < 16; bh++) {
        float a = 0.f;
#pragma unroll
        for (int r = 0; r < 16; r++) a += base[(bh * 16 + r) * 256];
        sm[bh * 256 + t] = a;
    }
    __syncthreads();
    int bh = t >> 4, bw = t & 15;
    float s = 0.f;
#pragma unroll
    for (int k = 0; k < 16; k++) s += sm[bh * 256 + bw * 16 + k];
    g_X[c * 256 + t] = s * (1.f / 256.f);
}

// ---------------- K1b: pool sup_y -> sel + compaction maps (fused) ----------------
__global__ void pool_y_sel_kernel(const float* __restrict__ sy) {
    int t = threadIdx.x;
    const float* base = sy + t;
    __shared__ float sm[16 * 256];
    __shared__ int ps[256];
#pragma unroll
    for (int bh = 0; bh < 16; bh++) {
        float a = 0.f;
#pragma unroll
        for (int r = 0; r < 16; r++) a += base[(bh * 16 + r) * 256];
        sm[bh * 256 + t] = a;
    }
    __syncthreads();
    int bh = t >> 4, bw = t & 15;
    float s = 0.f;
#pragma unroll
    for (int k = 0; k < 16; k++) s += sm[bh * 256 + bw * 16 + k];
    int sel = ((s * (1.f / 256.f)) > 0.5f) ? 1 : 0;
    g_sel[t] = (float)sel;
    ps[t] = sel;
    g_selidx[t] = 0;
    __syncthreads();
    if (t == 0) {
        int acc = 0;
        for (int n = 0; n < 256; n++) { int v = ps[n]; ps[n] = acc; acc += v; }
        g_S = acc;
    }
    __syncthreads();
    g_slot[t] = ps[t];
    if (sel) g_selidx[ps[t]] = t;
}

// ---------------- K2: w1 rows + softmax -> tridiagonal band (measured 19us) ----------------
#define BK_ROWS 4
__global__ __launch_bounds__(256) void band_kernel(const float* __restrict__ cal) {
    int t = threadIdx.x;
    int i0 = blockIdx.x * BK_ROWS;
    __shared__ float tile[256 * 33];
    __shared__ float wrow[BK_ROWS][256];
    float acc[BK_ROWS] = {0.f, 0.f, 0.f, 0.f};

    for (int k0 = 0; k0 < 256; k0 += 32) {
        __syncthreads();
#pragma unroll
        for (int it = 0; it < 32; it++) {
            int idx = t + it * 256;
            int r = idx >> 5, kk = idx & 31;
            tile[r * 33 + kk] = g_X[r * 256 + k0 + kk];
        }
        __syncthreads();
        float own[32];
#pragma unroll
        for (int kk = 0; kk < 32; kk++) own[kk] = tile[t * 33 + kk];
#pragma unroll
        for (int i = 0; i < BK_ROWS; i++) {
            const float* xi = &tile[(i0 + i) * 33];
            float a = acc[i];
#pragma unroll
            for (int kk = 0; kk < 32; kk++) a = fmaf(own[kk], xi[kk], a);
            acc[i] = a;
        }
    }
#pragma unroll
    for (int i = 0; i < BK_ROWS; i++) wrow[i][t] = acc[i];
    __syncthreads();

    int w = t >> 5, lane = t & 31;
    if (w < BK_ROWS) {
        int i = i0 + w;
        float mx = -CUDART_INF_F;
#pragma unroll
        for (int k = 0; k < 8; k++) mx = fmaxf(mx, wrow[w][k * 32 + lane]);
        mx = warp_max(mx);
        float s = 0.f;
#pragma unroll
        for (int k = 0; k < 8; k++) s += expf(wrow[w][k * 32 + lane] - mx);
        s = warp_sum(s);
        if (lane == 0) {
            float inv = 1.f / s;
            if (i > 0) {
                float e = expf(wrow[w][i - 1] - mx) * inv;
                g_mlo[i] = cal[i * 256 + (i - 1)] * (1.f + 0.2f * e);
            } else g_mlo[0] = 0.f;
            {
                float e = expf(wrow[w][i] - mx) * inv;
                g_mdi[i] = cal[i * 256 + i] * (1.f + 0.2f * e);
            }
            if (i < 255) {
                float e = expf(wrow[w][i + 1] - mx) * inv;
                g_mhi[i] = cal[i * 256 + (i + 1)] * (1.f + 0.2f * e);
            } else g_mhi[255] = 0.f;
        }
    }
}

// ---------------- K3: tridiag apply + col-normalize -> split tf32 planes [slot][c] ----------------
__global__ void proto_kernel() {
    int n = blockIdx.x, i = threadIdx.x;
    __shared__ float sred[40];
    float x0 = g_X[i * 256 + n];
    float xm = (i > 0)   ? g_X[(i - 1) * 256 + n] : 0.f;
    float xp = (i < 255) ? g_X[(i + 1) * 256 + n] : 0.f;
    float v = g_mlo[i] * xm + g_mdi[i] * x0 + g_mhi[i] * xp;
    float ss = blk_sum256(v * v, sred, i);
    float nrm = fmaxf(sqrtf(ss), 1e-4f);
    if (g_sel[n] > 0.f) {
        float pv = v / nrm;
        uint32_t h = f2tf32(pv);
        uint32_t l = f2tf32(pv - __uint_as_float(h));
        int s = g_slot[n];
        g_pH[s * 256 + i] = __uint_as_float(h);
        g_pL[s * 256 + i] = __uint_as_float(l);
    }
}

// ---------------- K4: tf32 mma.sync dist, 128px x 128slot tiles ----------------
// CTA = 128 px; per pass covers 128 compacted slots (2nd pass only if S>128).
// 8 warps as 4m x 2n; warp = 32px x 64slots; acc[2][8][4] = 64 f32.
// A[k][px] pitch 136 (conflict-free), B[slot][k] pitch 36 (conflict-free).
// D = qh*ph + qh*pl + ql*ph (tf32 3-term). Fragment maps verified in R11.
#define PXT 128
#define KC 32
#define PA 136
#define PB 36
#define PD 136
#define OFF_AH 0
#define OFF_AL 4352
#define OFF_BH 8704
#define OFF_BL 13312
#define OFF_STAT 17920
#define OFF_NRM  18944
#define OFF_SIDX 19072
#define DIST_FLOATS 19340
#define DIST_SMEM (DIST_FLOATS * 4)

__global__ __launch_bounds__(256) void dist_kernel(const float* __restrict__ qry,
                                                   float* __restrict__ out) {
    extern __shared__ float dsm[];
    int t = threadIdx.x;
    int warp = t >> 5, lane = t & 31;
    int g = lane >> 2, qd = lane & 3;
    int p0 = blockIdx.x * PXT;

    int* sidx = (int*)(dsm + OFF_SIDX);
    sidx[t] = g_selidx[t];
    int S = g_S;
    int npass = (S > 128) ? 2 : 1;

    float* stM = dsm + OFF_STAT;       // per-px merge stats (pass 0 -> pass 1)
    float* stE = stM + 128;
    float* stD = stE + 128;
    int*   stB = (int*)(stD + 128);

    int wm = warp & 3, wn = warp >> 2;
    int mbase = 32 * wm, nbase = 64 * wn;
    float4 ssv = make_float4(0.f, 0.f, 0.f, 0.f);
    const float NEG = -1e9f;

    for (int pass = 0; pass < npass; pass++) {
        int SB = pass * 128;
        float acc[2][8][4];
#pragma unroll
        for (int mt = 0; mt < 2; mt++)
#pragma unroll
            for (int nt = 0; nt < 8; nt++)
#pragma unroll
                for (int m = 0; m < 4; m++) acc[mt][nt][m] = 0.f;

        for (int ch = 0; ch < 8; ch++) {
            int k0 = ch * KC;
            // ---- stage A: 32 k-rows x 128 px, tf32 hi/lo split ----
            {
                int r0 = t >> 5, seg = t & 31;
#pragma unroll
                for (int i = 0; i < 4; i++) {
                    int r = r0 + 8 * i;
                    float4 v = *(const float4*)(qry + (size_t)(k0 + r) * HW + p0 + 4 * seg);
                    if (pass == 0) {
                        ssv.x = fmaf(v.x, v.x, ssv.x);
                        ssv.y = fmaf(v.y, v.y, ssv.y);
                        ssv.z = fmaf(v.z, v.z, ssv.z);
                        ssv.w = fmaf(v.w, v.w, ssv.w);
                    }
                    uint32_t hx = f2tf32(v.x), hy = f2tf32(v.y), hz = f2tf32(v.z), hw = f2tf32(v.w);
                    uint32_t lx = f2tf32(v.x - __uint_as_float(hx));
                    uint32_t ly = f2tf32(v.y - __uint_as_float(hy));
                    uint32_t lz = f2tf32(v.z - __uint_as_float(hz));
                    uint32_t lw = f2tf32(v.w - __uint_as_float(hw));
                    *(uint4*)(dsm + OFF_AH + r * PA + 4 * seg) = make_uint4(hx, hy, hz, hw);
                    *(uint4*)(dsm + OFF_AL + r * PA + 4 * seg) = make_uint4(lx, ly, lz, lw);
                }
            }
            // ---- stage B: 128 slots x 32 k, both planes ----
            {
#pragma unroll
                for (int i = 0; i < 8; i++) {
                    int id = t + 256 * i;
                    int plane = id >> 10;
                    int rem = id & 1023;
                    int slot = rem >> 3, sg = rem & 7;
                    const float* src = (plane ? g_pL : g_pH) + (size_t)(SB + slot) * 256 + k0 + 4 * sg;
                    float4 v = __ldg((const float4*)src);
                    *(float4*)(dsm + (plane ? OFF_BL : OFF_BH) + slot * PB + 4 * sg) = v;
                }
            }
            __syncthreads();
            // ---- mma over this chunk ----
            uint32_t* AH = (uint32_t*)(dsm + OFF_AH);
            uint32_t* AL = (uint32_t*)(dsm + OFF_AL);
            uint32_t* BH = (uint32_t*)(dsm + OFF_BH);
            uint32_t* BL = (uint32_t*)(dsm + OFF_BL);
#pragma unroll
            for (int ks = 0; ks < 4; ks++) {
                int klq = ks * 8 + qd;
                uint32_t ah[2][4], al[2][4];
#pragma unroll
                for (int mt = 0; mt < 2; mt++) {
                    int pxb = mbase + 16 * mt;
                    ah[mt][0] = AH[klq * PA + pxb + g];
                    ah[mt][1] = AH[klq * PA + pxb + g + 8];
                    ah[mt][2] = AH[(klq + 4) * PA + pxb + g];
                    ah[mt][3] = AH[(klq + 4) * PA + pxb + g + 8];
                    al[mt][0] = AL[klq * PA + pxb + g];
                    al[mt][1] = AL[klq * PA + pxb + g + 8];
                    al[mt][2] = AL[(klq + 4) * PA + pxb + g];
                    al[mt][3] = AL[(klq + 4) * PA + pxb + g + 8];
                }
#pragma unroll
                for (int nt = 0; nt < 8; nt++) {
                    int srow = nbase + 8 * nt + g;
                    uint32_t bh0 = BH[srow * PB + klq];
                    uint32_t bh1 = BH[srow * PB + klq + 4];
                    uint32_t bl0 = BL[srow * PB + klq];
                    uint32_t bl1 = BL[srow * PB + klq + 4];
#pragma unroll
                    for (int mt = 0; mt < 2; mt++) {
                        MMA_TF32(acc[mt][nt], ah[mt], bh0, bh1);
                        MMA_TF32(acc[mt][nt], ah[mt], bl0, bl1);
                        MMA_TF32(acc[mt][nt], al[mt], bh0, bh1);
                    }
                }
            }
            __syncthreads();
        }

        // ---- pass 0: reduce per-px sumsq -> nrm ----
        if (pass == 0) {
            int r0 = t >> 5, seg = t & 31;
            float* part = dsm + OFF_STAT;   // scratch before stats are live
            *(float4*)(part + (r0 * 32 + seg) * 4) = ssv;
            __syncthreads();
            if (t < 128) {
                float s = 0.f;
#pragma unroll
                for (int r = 0; r < 8; r++) s += part[(r * 32 + (t >> 2)) * 4 + (t & 3)];
                dsm[OFF_NRM + t] = fmaxf(sqrtf(s), 1e-4f);
            }
            __syncthreads();
        }

        // ---- write d-matrix (overlay A/B region) ----
        float* dbuf = dsm;
#pragma unroll
        for (int mt = 0; mt < 2; mt++) {
            int r0 = mbase + 16 * mt + g;
            int r1 = r0 + 8;
            float sc0 = 20.f / dsm[OFF_NRM + r0];
            float sc1 = 20.f / dsm[OFF_NRM + r1];
#pragma unroll
            for (int nt = 0; nt < 8; nt++) {
                int nloc = nbase + 8 * nt + 2 * qd;
                int ngl = SB + nloc;
                float d0 = (ngl     < S) ? acc[mt][nt][0] * sc0 : NEG;
                float d1 = (ngl + 1 < S) ? acc[mt][nt][1] * sc0 : NEG;
                float d2 = (ngl     < S) ? acc[mt][nt][2] * sc1 : NEG;
                float d3 = (ngl + 1 < S) ? acc[mt][nt][3] * sc1 : NEG;
                *(float2*)(dbuf + r0 * PD + nloc) = make_float2(d0, d1);
                *(float2*)(dbuf + r1 * PD + nloc) = make_float2(d2, d3);
            }
        }
        __syncthreads();

        // ---- epilogue: warp owns px 16*warp..+15 ----
        for (int pi = 0; pi < 16; pi++) {
            int px = warp * 16 + pi;
            const float* dp = dbuf + px * PD;
            float bm = -CUDART_INF_F; int bi = 0;
#pragma unroll
            for (int k = 0; k < 4; k++) {
                int n = k * 32 + lane;
                float v = dp[n];
                if (v > bm) { bm = v; bi = n; }
            }
#pragma unroll
            for (int o = 16; o; o >>= 1) {
                float om = __shfl_xor_sync(0xffffffffu, bm, o);
                int   oi = __shfl_xor_sync(0xffffffffu, bi, o);
                if (om > bm || (om == bm && oi < bi)) { bm = om; bi = oi; }
            }
            float se = 0.f, sd = 0.f;
#pragma unroll
            for (int k = 0; k < 4; k++) {
                float v = dp[k * 32 + lane];
                float e = fast_exp_neg(v - bm);
                se += e; sd += e * v;
            }
            se = warp_sum(se); sd = warp_sum(sd);
            if (lane == 0) {
                if (npass == 1) {
                    if (S == 0) { out[p0 + px] = NEG; out[HW + p0 + px] = 0.f; }
                    else        { out[p0 + px] = sd / se; out[HW + p0 + px] = (float)sidx[bi]; }
                } else if (pass == 0) {
                    stM[px] = bm; stE[px] = se; stD[px] = sd; stB[px] = bi;
                } else {
                    float bm0 = stM[px], se0 = stE[px], sd0 = stD[px];
                    int bi0 = stB[px];
                    int big = 128 + bi;
                    float M = fmaxf(bm0, bm);
                    int bif = (bm > bm0) ? big : bi0;     // pass0 wins ties (lower index)
                    float ra = fast_exp_neg(bm0 - M), rb = fast_exp_neg(bm - M);
                    float seT = se0 * ra + se * rb;
                    float sdT = sd0 * ra + sd * rb;
                    out[p0 + px]      = sdT / seT;
                    out[HW + p0 + px] = (float)sidx[bif];
                }
            }
        }
        __syncthreads();
    }
}

// ---------------- launcher ----------------
extern "C" void kernel_launch(void* const* d_in, const int* in_sizes, int n_in,
                              void* d_out, int out_size) {
    const float* qry   = (const float*)d_in[0];
    const float* sup_x = (const float*)d_in[1];
    const float* sup_y = (const float*)d_in[2];
    const float* cal   = (const float*)d_in[4];
    float* out = (float*)d_out;

    cudaFuncSetAttribute(dist_kernel, cudaFuncAttributeMaxDynamicSharedMemorySize, DIST_SMEM);

    pool_x_kernel<<<256, 256>>>(sup_x);
    pool_y_sel_kernel<<<1, 256>>>(sup_y);
    band_kernel<<<64, 256>>>(cal);
    proto_kernel<<<256, 256>>>();
    dist_kernel<<<HW / PXT, 256, DIST_SMEM>>>(qry, out);
}

// round 15
// speedup vs baseline: 3.6044x; 1.1931x over previous
#include <cuda_runtime.h>
#include <cuda_bf16.h>
#include <math_constants.h>
#include <cstdint>

#define CCH 256
#define HW  65536     // 256*256 pixels

// ---------------- scratch (no allocations allowed) ----------------
__device__ float g_X[CCH * 256];        // X[c][n]
__device__ uint32_t g_pHp[256 * 128];   // proto hi plane [slot][kp] bf16x2 (c=2kp,2kp+1)
__device__ uint32_t g_pLp[256 * 128];   // proto lo plane [slot][kp] bf16x2
__device__ float g_mlo[CCH], g_mdi[CCH], g_mhi[CCH];
__device__ float g_sel[256];
__device__ int   g_slot[256];
__device__ int   g_selidx[256];
__device__ int   g_S;

// ---------------- helpers ----------------
__device__ __forceinline__ float warp_sum(float v) {
#pragma unroll
    for (int o = 16; o; o >>= 1) v += __shfl_xor_sync(0xffffffffu, v, o);
    return v;
}
__device__ __forceinline__ float warp_max(float v) {
#pragma unroll
    for (int o = 16; o; o >>= 1) v = fmaxf(v, __shfl_xor_sync(0xffffffffu, v, o));
    return v;
}
__device__ __forceinline__ float blk_sum256(float v, float* s, int t) {
    v = warp_sum(v);
    __syncthreads();
    if ((t & 31) == 0) s[t >> 5] = v;
    __syncthreads();
    if (t < 32) {
        float x = (t < 8) ? s[t] : 0.f;
        x = warp_sum(x);
        if (t == 0) s[32] = x;
    }
    __syncthreads();
    float r = s[32];
    __syncthreads();
    return r;
}

// exp(x) for x <= 0 on the FMA pipe (no MUFU)
__device__ __forceinline__ float fast_exp_neg(float x) {
    x = fmaxf(x, -87.f);
    float t = x * 1.44269504088896340736f;
    float n = rintf(t);
    float r = t - n;
    float p = 1.540353039338161e-4f;
    p = fmaf(p, r, 1.3333558146428443e-3f);
    p = fmaf(p, r, 9.618129107628477e-3f);
    p = fmaf(p, r, 5.550410866482158e-2f);
    p = fmaf(p, r, 2.402265069591007e-1f);
    p = fmaf(p, r, 6.931471805599453e-1f);
    p = fmaf(p, r, 1.0f);
    float s = __int_as_float(((int)n + 127) << 23);
    return p * s;
}

// pack two floats to bf16x2 (lo half = first arg) and return residuals
__device__ __forceinline__ uint32_t pack_bf2(float a, float b, float& ra, float& rb) {
    __nv_bfloat162 h = __floats2bfloat162_rn(a, b);
    float2 f = __bfloat1622float2(h);
    ra = a - f.x;
    rb = b - f.y;
    return *(uint32_t*)&h;
}
__device__ __forceinline__ uint32_t pack_bf2n(float a, float b) {
    __nv_bfloat162 h = __floats2bfloat162_rn(a, b);
    return *(uint32_t*)&h;
}

#define MMA_BF16(d, a, b0, b1) \
    asm("mma.sync.aligned.m16n8k16.row.col.f32.bf16.bf16.f32 " \
        "{%0,%1,%2,%3}, {%4,%5,%6,%7}, {%8,%9}, {%0,%1,%2,%3};" \
        : "+f"((d)[0]), "+f"((d)[1]), "+f"((d)[2]), "+f"((d)[3]) \
        : "r"((a)[0]), "r"((a)[1]), "r"((a)[2]), "r"((a)[3]), "r"(b0), "r"(b1))

// ---------------- K1a: pool sup_x -> g_X[c][n] ----------------
__global__ void pool_x_kernel(const float* __restrict__ sx) {
    int c = blockIdx.x, t = threadIdx.x;
    const float* base = sx + (size_t)c * HW + t;
    __shared__ float sm[16 * 256];
#pragma unroll
    for (int bh = 0; bh < 16; bh++) {
        float a = 0.f;
#pragma unroll
        for (int r = 0; r < 16; r++) a += base[(bh * 16 + r) * 256];
        sm[bh * 256 + t] = a;
    }
    __syncthreads();
    int bh = t >> 4, bw = t & 15;
    float s = 0.f;
#pragma unroll
    for (int k = 0; k < 16; k++) s += sm[bh * 256 + bw * 16 + k];
    g_X[c * 256 + t] = s * (1.f / 256.f);
}

// ---------------- K1b: pool sup_y -> sel + compaction maps (fused) ----------------
__global__ void pool_y_sel_kernel(const float* __restrict__ sy) {
    int t = threadIdx.x;
    const float* base = sy + t;
    __shared__ float sm[16 * 256];
    __shared__ int ps[256];
#pragma unroll
    for (int bh = 0; bh < 16; bh++) {
        float a = 0.f;
#pragma unroll
        for (int r = 0; r < 16; r++) a += base[(bh * 16 + r) * 256];
        sm[bh * 256 + t] = a;
    }
    __syncthreads();
    int bh = t >> 4, bw = t & 15;
    float s = 0.f;
#pragma unroll
    for (int k = 0; k < 16; k++) s += sm[bh * 256 + bw * 16 + k];
    int sel = ((s * (1.f / 256.f)) > 0.5f) ? 1 : 0;
    g_sel[t] = (float)sel;
    ps[t] = sel;
    g_selidx[t] = 0;
    __syncthreads();
    if (t == 0) {
        int acc = 0;
        for (int n = 0; n < 256; n++) { int v = ps[n]; ps[n] = acc; acc += v; }
        g_S = acc;
    }
    __syncthreads();
    g_slot[t] = ps[t];
    if (sel) g_selidx[ps[t]] = t;
}

// ---------------- K2: w1 rows + softmax -> tridiagonal band (measured 19us) ----------------
#define BK_ROWS 4
__global__ __launch_bounds__(256) void band_kernel(const float* __restrict__ cal) {
    int t = threadIdx.x;
    int i0 = blockIdx.x * BK_ROWS;
    __shared__ float tile[256 * 33];
    __shared__ float wrow[BK_ROWS][256];
    float acc[BK_ROWS] = {0.f, 0.f, 0.f, 0.f};

    for (int k0 = 0; k0 < 256; k0 += 32) {
        __syncthreads();
#pragma unroll
        for (int it = 0; it < 32; it++) {
            int idx = t + it * 256;
            int r = idx >> 5, kk = idx & 31;
            tile[r * 33 + kk] = g_X[r * 256 + k0 + kk];
        }
        __syncthreads();
        float own[32];
#pragma unroll
        for (int kk = 0; kk < 32; kk++) own[kk] = tile[t * 33 + kk];
#pragma unroll
        for (int i = 0; i < BK_ROWS; i++) {
            const float* xi = &tile[(i0 + i) * 33];
            float a = acc[i];
#pragma unroll
            for (int kk = 0; kk < 32; kk++) a = fmaf(own[kk], xi[kk], a);
            acc[i] = a;
        }
    }
#pragma unroll
    for (int i = 0; i < BK_ROWS; i++) wrow[i][t] = acc[i];
    __syncthreads();

    int w = t >> 5, lane = t & 31;
    if (w < BK_ROWS) {
        int i = i0 + w;
        float mx = -CUDART_INF_F;
#pragma unroll
        for (int k = 0; k < 8; k++) mx = fmaxf(mx, wrow[w][k * 32 + lane]);
        mx = warp_max(mx);
        float s = 0.f;
#pragma unroll
        for (int k = 0; k < 8; k++) s += expf(wrow[w][k * 32 + lane] - mx);
        s = warp_sum(s);
        if (lane == 0) {
            float inv = 1.f / s;
            if (i > 0) {
                float e = expf(wrow[w][i - 1] - mx) * inv;
                g_mlo[i] = cal[i * 256 + (i - 1)] * (1.f + 0.2f * e);
            } else g_mlo[0] = 0.f;
            {
                float e = expf(wrow[w][i] - mx) * inv;
                g_mdi[i] = cal[i * 256 + i] * (1.f + 0.2f * e);
            }
            if (i < 255) {
                float e = expf(wrow[w][i + 1] - mx) * inv;
                g_mhi[i] = cal[i * 256 + (i + 1)] * (1.f + 0.2f * e);
            } else g_mhi[255] = 0.f;
        }
    }
}

// ---------------- K3: tridiag apply + col-normalize -> packed bf16 hi/lo planes ----------------
__global__ void proto_kernel() {
    int n = blockIdx.x, i = threadIdx.x;
    __shared__ float sred[40];
    __shared__ float spv[256];
    float x0 = g_X[i * 256 + n];
    float xm = (i > 0)   ? g_X[(i - 1) * 256 + n] : 0.f;
    float xp = (i < 255) ? g_X[(i + 1) * 256 + n] : 0.f;
    float v = g_mlo[i] * xm + g_mdi[i] * x0 + g_mhi[i] * xp;
    float ss = blk_sum256(v * v, sred, i);
    float nrm = fmaxf(sqrtf(ss), 1e-4f);
    spv[i] = v / nrm;
    __syncthreads();
    if (g_sel[n] > 0.f && i < 128) {
        int s = g_slot[n];
        float a = spv[2 * i], b = spv[2 * i + 1];
        float ra, rb;
        uint32_t h = pack_bf2(a, b, ra, rb);
        uint32_t l = pack_bf2n(ra, rb);
        g_pHp[s * 128 + i] = h;
        g_pLp[s * 128 + i] = l;
    }
}

// ---------------- K4: bf16 4-term split mma.sync dist, 128px x 128slot tiles ----------------
// CTA = 128 px; per pass 128 compacted slots (2nd pass only if S>128).
// 8 warps = 4m x 2n; warp = 32px x 64slots. KC=64 (4 chunks, 4 k16-steps each).
// D = qh*ph + qh*pl + ql*ph + ql*pl: every bf16 product is EXACT in fp32, so
// the only error is fp32 accumulation (~1e-7) -> argmax-safe (R13 lesson).
#define PXT 128
#define PA 136
#define PB 36
#define PD 136
#define OFF_AH 0
#define OFF_AL 4352
#define OFF_BH 8704
#define OFF_BL 13312
#define OFF_STAT 17920
#define OFF_NRM  18944
#define OFF_SIDX 19072
#define DIST_FLOATS 19340
#define DIST_SMEM (DIST_FLOATS * 4)

__global__ __launch_bounds__(256) void dist_kernel(const float* __restrict__ qry,
                                                   float* __restrict__ out) {
    extern __shared__ float dsm[];
    int t = threadIdx.x;
    int warp = t >> 5, lane = t & 31;
    int g = lane >> 2, qd = lane & 3;
    int p0 = blockIdx.x * PXT;

    int* sidx = (int*)(dsm + OFF_SIDX);
    sidx[t] = g_selidx[t];
    int S = g_S;
    int npass = (S > 128) ? 2 : 1;

    float* stM = dsm + OFF_STAT;
    float* stE = stM + 128;
    float* stD = stE + 128;
    int*   stB = (int*)(stD + 128);

    int wm = warp & 3, wn = warp >> 2;
    int mbase = 32 * wm, nbase = 64 * wn;
    float4 ssv = make_float4(0.f, 0.f, 0.f, 0.f);
    const float NEG = -1e9f;

    uint32_t* AH = (uint32_t*)(dsm + OFF_AH);
    uint32_t* AL = (uint32_t*)(dsm + OFF_AL);
    uint32_t* BH = (uint32_t*)(dsm + OFF_BH);
    uint32_t* BL = (uint32_t*)(dsm + OFF_BL);

    for (int pass = 0; pass < npass; pass++) {
        int SB = pass * 128;
        float acc[2][8][4];
#pragma unroll
        for (int mt = 0; mt < 2; mt++)
#pragma unroll
            for (int nt = 0; nt < 8; nt++)
#pragma unroll
                for (int m = 0; m < 4; m++) acc[mt][nt][m] = 0.f;

        for (int ch = 0; ch < 4; ch++) {
            int k0 = ch * 64;
            // ---- stage A: 64 k rows -> 32 kp-pairs x 128 px, bf16x2 hi/lo ----
            {
                int kp0 = t >> 5, seg = t & 31;
#pragma unroll
                for (int i = 0; i < 4; i++) {
                    int kp = kp0 + 8 * i;
                    const float* q0 = qry + (size_t)(k0 + 2 * kp) * HW + p0 + 4 * seg;
                    float4 v0 = *(const float4*)q0;
                    float4 v1 = *(const float4*)(q0 + HW);
                    if (pass == 0) {
                        ssv.x += v0.x * v0.x + v1.x * v1.x;
                        ssv.y += v0.y * v0.y + v1.y * v1.y;
                        ssv.z += v0.z * v0.z + v1.z * v1.z;
                        ssv.w += v0.w * v0.w + v1.w * v1.w;
                    }
                    float rx0, rx1, ry0, ry1, rz0, rz1, rw0, rw1;
                    uint32_t hx = pack_bf2(v0.x, v1.x, rx0, rx1);
                    uint32_t hy = pack_bf2(v0.y, v1.y, ry0, ry1);
                    uint32_t hz = pack_bf2(v0.z, v1.z, rz0, rz1);
                    uint32_t hw = pack_bf2(v0.w, v1.w, rw0, rw1);
                    uint32_t lx = pack_bf2n(rx0, rx1);
                    uint32_t ly = pack_bf2n(ry0, ry1);
                    uint32_t lz = pack_bf2n(rz0, rz1);
                    uint32_t lw = pack_bf2n(rw0, rw1);
                    *(uint4*)(AH + kp * PA + 4 * seg) = make_uint4(hx, hy, hz, hw);
                    *(uint4*)(AL + kp * PA + 4 * seg) = make_uint4(lx, ly, lz, lw);
                }
            }
            // ---- stage B: copy pre-packed planes, 128 slots x 32 kp ----
#pragma unroll
            for (int i = 0; i < 8; i++) {
                int id = t + 256 * i;
                int plane = id >> 10;
                int rem = id & 1023;
                int slot = rem >> 3, sg = rem & 7;
                const uint4* src = (const uint4*)((plane ? g_pLp : g_pHp) + (size_t)(SB + slot) * 128 + ch * 32) + sg;
                uint4 v = __ldg(src);
                *(uint4*)((plane ? BL : BH) + slot * PB + 4 * sg) = v;
            }
            __syncthreads();
            // ---- mma: 4 k16 steps per chunk, 4-term split ----
#pragma unroll
            for (int ks = 0; ks < 4; ks++) {
                int kq = ks * 8 + qd;
                uint32_t ah[2][4], al[2][4];
#pragma unroll
                for (int mt = 0; mt < 2; mt++) {
                    int pxb = mbase + 16 * mt;
                    ah[mt][0] = AH[kq * PA + pxb + g];
                    ah[mt][1] = AH[kq * PA + pxb + g + 8];
                    ah[mt][2] = AH[(kq + 4) * PA + pxb + g];
                    ah[mt][3] = AH[(kq + 4) * PA + pxb + g + 8];
                    al[mt][0] = AL[kq * PA + pxb + g];
                    al[mt][1] = AL[kq * PA + pxb + g + 8];
                    al[mt][2] = AL[(kq + 4) * PA + pxb + g];
                    al[mt][3] = AL[(kq + 4) * PA + pxb + g + 8];
                }
#pragma unroll
                for (int nt = 0; nt < 8; nt++) {
                    int srow = nbase + 8 * nt + g;
                    uint32_t bh0 = BH[srow * PB + kq];
                    uint32_t bh1 = BH[srow * PB + kq + 4];
                    uint32_t bl0 = BL[srow * PB + kq];
                    uint32_t bl1 = BL[srow * PB + kq + 4];
#pragma unroll
                    for (int mt = 0; mt < 2; mt++) {
                        MMA_BF16(acc[mt][nt], ah[mt], bh0, bh1);
                        MMA_BF16(acc[mt][nt], ah[mt], bl0, bl1);
                        MMA_BF16(acc[mt][nt], al[mt], bh0, bh1);
                        MMA_BF16(acc[mt][nt], al[mt], bl0, bl1);
                    }
                }
            }
            __syncthreads();
        }

        // ---- pass 0: reduce per-px sumsq -> nrm ----
        if (pass == 0) {
            int r0 = t >> 5, seg = t & 31;
            float* part = dsm + OFF_STAT;
            *(float4*)(part + (r0 * 32 + seg) * 4) = ssv;
            __syncthreads();
            if (t < 128) {
                float s = 0.f;
#pragma unroll
                for (int r = 0; r < 8; r++) s += part[(r * 32 + (t >> 2)) * 4 + (t & 3)];
                dsm[OFF_NRM + t] = fmaxf(sqrtf(s), 1e-4f);
            }
            __syncthreads();
        }

        // ---- write d-matrix (overlay A/B region) ----
        float* dbuf = dsm;
#pragma unroll
        for (int mt = 0; mt < 2; mt++) {
            int r0 = mbase + 16 * mt + g;
            int r1 = r0 + 8;
            float sc0 = 20.f / dsm[OFF_NRM + r0];
            float sc1 = 20.f / dsm[OFF_NRM + r1];
#pragma unroll
            for (int nt = 0; nt < 8; nt++) {
                int nloc = nbase + 8 * nt + 2 * qd;
                int ngl = SB + nloc;
                float d0 = (ngl     < S) ? acc[mt][nt][0] * sc0 : NEG;
                float d1 = (ngl + 1 < S) ? acc[mt][nt][1] * sc0 : NEG;
                float d2 = (ngl     < S) ? acc[mt][nt][2] * sc1 : NEG;
                float d3 = (ngl + 1 < S) ? acc[mt][nt][3] * sc1 : NEG;
                *(float2*)(dbuf + r0 * PD + nloc) = make_float2(d0, d1);
                *(float2*)(dbuf + r1 * PD + nloc) = make_float2(d2, d3);
            }
        }
        __syncthreads();

        // ---- epilogue: warp owns px 16*warp..+15 ----
        for (int pi = 0; pi < 16; pi++) {
            int px = warp * 16 + pi;
            const float* dp = dbuf + px * PD;
            float bm = -CUDART_INF_F; int bi = 0;
#pragma unroll
            for (int k = 0; k < 4; k++) {
                int n = k * 32 + lane;
                float v = dp[n];
                if (v > bm) { bm = v; bi = n; }
            }
#pragma unroll
            for (int o = 16; o; o >>= 1) {
                float om = __shfl_xor_sync(0xffffffffu, bm, o);
                int   oi = __shfl_xor_sync(0xffffffffu, bi, o);
                if (om > bm || (om == bm && oi < bi)) { bm = om; bi = oi; }
            }
            float se = 0.f, sd = 0.f;
#pragma unroll
            for (int k = 0; k < 4; k++) {
                float v = dp[k * 32 + lane];
                float e = fast_exp_neg(v - bm);
                se += e; sd += e * v;
            }
            se = warp_sum(se); sd = warp_sum(sd);
            if (lane == 0) {
                if (npass == 1) {
                    if (S == 0) { out[p0 + px] = NEG; out[HW + p0 + px] = 0.f; }
                    else        { out[p0 + px] = sd / se; out[HW + p0 + px] = (float)sidx[bi]; }
                } else if (pass == 0) {
                    stM[px] = bm; stE[px] = se; stD[px] = sd; stB[px] = bi;
                } else {
                    float bm0 = stM[px], se0 = stE[px], sd0 = stD[px];
                    int bi0 = stB[px];
                    int big = 128 + bi;
                    float M = fmaxf(bm0, bm);
                    int bif = (bm > bm0) ? big : bi0;     // pass0 wins ties (lower index)
                    float ra = fast_exp_neg(bm0 - M), rb = fast_exp_neg(bm - M);
                    float seT = se0 * ra + se * rb;
                    float sdT = sd0 * ra + sd * rb;
                    out[p0 + px]      = sdT / seT;
                    out[HW + p0 + px] = (float)sidx[bif];
                }
            }
        }
        __syncthreads();
    }
}

// ---------------- launcher ----------------
extern "C" void kernel_launch(void* const* d_in, const int* in_sizes, int n_in,
                              void* d_out, int out_size) {
    const float* qry   = (const float*)d_in[0];
    const float* sup_x = (const float*)d_in[1];
    const float* sup_y = (const float*)d_in[2];
    const float* cal   = (const float*)d_in[4];
    float* out = (float*)d_out;

    cudaFuncSetAttribute(dist_kernel, cudaFuncAttributeMaxDynamicSharedMemorySize, DIST_SMEM);

    pool_x_kernel<<<256, 256>>>(sup_x);
    pool_y_sel_kernel<<<1, 256>>>(sup_y);
    band_kernel<<<64, 256>>>(cal);
    proto_kernel<<<256, 256>>>();
    dist_kernel<<<HW / PXT, 256, DIST_SMEM>>>(qry, out);
}

// round 16
// speedup vs baseline: 3.8477x; 1.0675x over previous
#include <cuda_runtime.h>
#include <cuda_fp16.h>
#include <math_constants.h>
#include <cstdint>

#define CCH 256
#define HW  65536     // 256*256 pixels

// ---------------- scratch (no allocations allowed) ----------------
__device__ float g_X[CCH * 256];        // X[c][n]
__device__ float g_XT[256 * CCH];       // XT[n][c] = X[c][n]
__device__ uint32_t g_pHp[256 * 128];   // proto hi plane [slot][kp] f16x2 (c=2kp,2kp+1)
__device__ uint32_t g_pLp[256 * 128];   // proto lo plane [slot][kp] f16x2
__device__ float g_mlo[CCH], g_mdi[CCH], g_mhi[CCH];
__device__ float g_sel[256];
__device__ int   g_slot[256];
__device__ int   g_selidx[256];
__device__ int   g_S;

// ---------------- helpers ----------------
__device__ __forceinline__ float warp_sum(float v) {
#pragma unroll
    for (int o = 16; o; o >>= 1) v += __shfl_xor_sync(0xffffffffu, v, o);
    return v;
}
__device__ __forceinline__ float warp_max(float v) {
#pragma unroll
    for (int o = 16; o; o >>= 1) v = fmaxf(v, __shfl_xor_sync(0xffffffffu, v, o));
    return v;
}
__device__ __forceinline__ float blk_sum256(float v, float* s, int t) {
    v = warp_sum(v);
    __syncthreads();
    if ((t & 31) == 0) s[t >> 5] = v;
    __syncthreads();
    if (t < 32) {
        float x = (t < 8) ? s[t] : 0.f;
        x = warp_sum(x);
        if (t == 0) s[32] = x;
    }
    __syncthreads();
    float r = s[32];
    __syncthreads();
    return r;
}
__device__ __forceinline__ float blk_max256(float v, float* s, int t) {
    v = warp_max(v);
    __syncthreads();
    if ((t & 31) == 0) s[t >> 5] = v;
    __syncthreads();
    if (t < 32) {
        float x = (t < 8) ? s[t] : -CUDART_INF_F;
        x = warp_max(x);
        if (t == 0) s[32] = x;
    }
    __syncthreads();
    float r = s[32];
    __syncthreads();
    return r;
}

// exp(x) for x <= 0 on the FMA pipe (no MUFU)
__device__ __forceinline__ float fast_exp_neg(float x) {
    x = fmaxf(x, -87.f);
    float t = x * 1.44269504088896340736f;
    float n = rintf(t);
    float r = t - n;
    float p = 1.540353039338161e-4f;
    p = fmaf(p, r, 1.3333558146428443e-3f);
    p = fmaf(p, r, 9.618129107628477e-3f);
    p = fmaf(p, r, 5.550410866482158e-2f);
    p = fmaf(p, r, 2.402265069591007e-1f);
    p = fmaf(p, r, 6.931471805599453e-1f);
    p = fmaf(p, r, 1.0f);
    float s = __int_as_float(((int)n + 127) << 23);
    return p * s;
}

// pack two floats to f16x2 (lo half = first arg) and return residuals
__device__ __forceinline__ uint32_t pack_h2(float a, float b, float& ra, float& rb) {
    __half2 h = __floats2half2_rn(a, b);
    float2 f = __half22float2(h);
    ra = a - f.x;
    rb = b - f.y;
    return *(uint32_t*)&h;
}
__device__ __forceinline__ uint32_t pack_h2n(float a, float b) {
    __half2 h = __floats2half2_rn(a, b);
    return *(uint32_t*)&h;
}

#define MMA_F16(d, a, b0, b1) \
    asm("mma.sync.aligned.m16n8k16.row.col.f32.f16.f16.f32 " \
        "{%0,%1,%2,%3}, {%4,%5,%6,%7}, {%8,%9}, {%0,%1,%2,%3};" \
        : "+f"((d)[0]), "+f"((d)[1]), "+f"((d)[2]), "+f"((d)[3]) \
        : "r"((a)[0]), "r"((a)[1]), "r"((a)[2]), "r"((a)[3]), "r"(b0), "r"(b1))

// ---------------- K1a: pool sup_x -> g_X[c][n] + g_XT[n][c] ----------------
__global__ void pool_x_kernel(const float* __restrict__ sx) {
    int c = blockIdx.x, t = threadIdx.x;
    const float* base = sx + (size_t)c * HW + t;
    __shared__ float sm[16 * 256];
#pragma unroll
    for (int bh = 0; bh < 16; bh++) {
        float a = 0.f;
#pragma unroll
        for (int r = 0; r < 16; r++) a += base[(bh * 16 + r) * 256];
        sm[bh * 256 + t] = a;
    }
    __syncthreads();
    int bh = t >> 4, bw = t & 15;
    float s = 0.f;
#pragma unroll
    for (int k = 0; k < 16; k++) s += sm[bh * 256 + bw * 16 + k];
    float v = s * (1.f / 256.f);
    g_X[c * 256 + t] = v;
    g_XT[t * 256 + c] = v;
}

// ---------------- K1b: pool sup_y -> sel + compaction maps (fused) ----------------
__global__ void pool_y_sel_kernel(const float* __restrict__ sy) {
    int t = threadIdx.x;
    const float* base = sy + t;
    __shared__ float sm[16 * 256];
    __shared__ int ps[256];
#pragma unroll
    for (int bh = 0; bh < 16; bh++) {
        float a = 0.f;
#pragma unroll
        for (int r = 0; r < 16; r++) a += base[(bh * 16 + r) * 256];
        sm[bh * 256 + t] = a;
    }
    __syncthreads();
    int bh = t >> 4, bw = t & 15;
    float s = 0.f;
#pragma unroll
    for (int k = 0; k < 16; k++) s += sm[bh * 256 + bw * 16 + k];
    int sel = ((s * (1.f / 256.f)) > 0.5f) ? 1 : 0;
    g_sel[t] = (float)sel;
    ps[t] = sel;
    g_selidx[t] = 0;
    __syncthreads();
    if (t == 0) {
        int acc = 0;
        for (int n = 0; n < 256; n++) { int v = ps[n]; ps[n] = acc; acc += v; }
        g_S = acc;
    }
    __syncthreads();
    g_slot[t] = ps[t];
    if (sel) g_selidx[ps[t]] = t;
}

// ---------------- K2: w1 row + softmax -> band (XT-based, 256 blocks, coalesced) ----------------
__global__ __launch_bounds__(256) void band_kernel(const float* __restrict__ cal) {
    int i = blockIdx.x, t = threadIdx.x;
    __shared__ float xi[256];
    __shared__ float sred[40];
    xi[t] = g_XT[t * 256 + i];            // X[i, t]
    __syncthreads();
    const float* xtp = g_XT + t;          // XT[n][t]: lane-coalesced per n
    float w = 0.f;
#pragma unroll 8
    for (int n = 0; n < 256; n++) w = fmaf(__ldg(xtp + n * 256), xi[n], w);
    float mx = blk_max256(w, sred, t);
    float e = expf(w - mx);
    float Sm = blk_sum256(e, sred, t);
    if (t >= i - 1 && t <= i + 1) {
        float s = e / Sm;
        float m = cal[i * 256 + t] * (1.f + 0.2f * s);
        if (t == i - 1) g_mlo[i] = m;
        else if (t == i) g_mdi[i] = m;
        else g_mhi[i] = m;
    }
    if (t == 0) {
        if (i == 0)   g_mlo[0]   = 0.f;
        if (i == 255) g_mhi[255] = 0.f;
    }
}

// ---------------- K3: tridiag apply + col-normalize -> packed f16 hi/lo planes ----------------
__global__ void proto_kernel() {
    int n = blockIdx.x, i = threadIdx.x;
    __shared__ float sred[40];
    __shared__ float spv[256];
    float x0 = g_X[i * 256 + n];
    float xm = (i > 0)   ? g_X[(i - 1) * 256 + n] : 0.f;
    float xp = (i < 255) ? g_X[(i + 1) * 256 + n] : 0.f;
    float v = g_mlo[i] * xm + g_mdi[i] * x0 + g_mhi[i] * xp;
    float ss = blk_sum256(v * v, sred, i);
    float nrm = fmaxf(sqrtf(ss), 1e-4f);
    spv[i] = v / nrm;
    __syncthreads();
    if (g_sel[n] > 0.f && i < 128) {
        int s = g_slot[n];
        float a = spv[2 * i], b = spv[2 * i + 1];
        float ra, rb;
        uint32_t h = pack_h2(a, b, ra, rb);
        uint32_t l = pack_h2n(ra, rb);
        g_pHp[s * 128 + i] = h;
        g_pLp[s * 128 + i] = l;
    }
}

// ---------------- K4: fp16 3-term split mma.sync dist, 128px x 128slot tiles ----------------
// CTA = 128 px; per pass 128 compacted slots (2nd pass only if S>128).
// 8 warps = 4m x 2n; warp = 32px x 64slots. KC=64 (4 chunks, 4 k16-steps each).
// D = qh*ph + qh*pl + ql*ph; dropped ql*pl ~2^-24/product -> dist err ~1e-7-scale
// (256x below the bf16-3-term failure level). fp16 products exact in fp32.
#define PXT 128
#define PA 136
#define PB 36
#define PD 136
#define OFF_AH 0
#define OFF_AL 4352
#define OFF_BH 8704
#define OFF_BL 13312
#define OFF_STAT 17920
#define OFF_NRM  18944
#define OFF_SIDX 19072
#define DIST_FLOATS 19340
#define DIST_SMEM (DIST_FLOATS * 4)

__global__ __launch_bounds__(256) void dist_kernel(const float* __restrict__ qry,
                                                   float* __restrict__ out) {
    extern __shared__ float dsm[];
    int t = threadIdx.x;
    int warp = t >> 5, lane = t & 31;
    int g = lane >> 2, qd = lane & 3;
    int p0 = blockIdx.x * PXT;

    int* sidx = (int*)(dsm + OFF_SIDX);
    sidx[t] = g_selidx[t];
    int S = g_S;
    int npass = (S > 128) ? 2 : 1;

    float* stM = dsm + OFF_STAT;
    float* stE = stM + 128;
    float* stD = stE + 128;
    int*   stB = (int*)(stD + 128);

    int wm = warp & 3, wn = warp >> 2;
    int mbase = 32 * wm, nbase = 64 * wn;
    float4 ssv = make_float4(0.f, 0.f, 0.f, 0.f);
    const float NEG = -1e9f;

    uint32_t* AH = (uint32_t*)(dsm + OFF_AH);
    uint32_t* AL = (uint32_t*)(dsm + OFF_AL);
    uint32_t* BH = (uint32_t*)(dsm + OFF_BH);
    uint32_t* BL = (uint32_t*)(dsm + OFF_BL);

    for (int pass = 0; pass < npass; pass++) {
        int SB = pass * 128;
        float acc[2][8][4];
#pragma unroll
        for (int mt = 0; mt < 2; mt++)
#pragma unroll
            for (int nt = 0; nt < 8; nt++)
#pragma unroll
                for (int m = 0; m < 4; m++) acc[mt][nt][m] = 0.f;

        for (int ch = 0; ch < 4; ch++) {
            int k0 = ch * 64;
            // ---- stage A: 64 k rows -> 32 kp-pairs x 128 px, f16x2 hi/lo ----
            {
                int kp0 = t >> 5, seg = t & 31;
#pragma unroll
                for (int i = 0; i < 4; i++) {
                    int kp = kp0 + 8 * i;
                    const float* q0 = qry + (size_t)(k0 + 2 * kp) * HW + p0 + 4 * seg;
                    float4 v0 = *(const float4*)q0;
                    float4 v1 = *(const float4*)(q0 + HW);
                    if (pass == 0) {
                        ssv.x += v0.x * v0.x + v1.x * v1.x;
                        ssv.y += v0.y * v0.y + v1.y * v1.y;
                        ssv.z += v0.z * v0.z + v1.z * v1.z;
                        ssv.w += v0.w * v0.w + v1.w * v1.w;
                    }
                    float rx0, rx1, ry0, ry1, rz0, rz1, rw0, rw1;
                    uint32_t hx = pack_h2(v0.x, v1.x, rx0, rx1);
                    uint32_t hy = pack_h2(v0.y, v1.y, ry0, ry1);
                    uint32_t hz = pack_h2(v0.z, v1.z, rz0, rz1);
                    uint32_t hw = pack_h2(v0.w, v1.w, rw0, rw1);
                    uint32_t lx = pack_h2n(rx0, rx1);
                    uint32_t ly = pack_h2n(ry0, ry1);
                    uint32_t lz = pack_h2n(rz0, rz1);
                    uint32_t lw = pack_h2n(rw0, rw1);
                    *(uint4*)(AH + kp * PA + 4 * seg) = make_uint4(hx, hy, hz, hw);
                    *(uint4*)(AL + kp * PA + 4 * seg) = make_uint4(lx, ly, lz, lw);
                }
            }
            // ---- stage B: copy pre-packed planes, 128 slots x 32 kp ----
#pragma unroll
            for (int i = 0; i < 8; i++) {
                int id = t + 256 * i;
                int plane = id >> 10;
                int rem = id & 1023;
                int slot = rem >> 3, sg = rem & 7;
                const uint4* src = (const uint4*)((plane ? g_pLp : g_pHp) + (size_t)(SB + slot) * 128 + ch * 32) + sg;
                uint4 v = __ldg(src);
                *(uint4*)((plane ? BL : BH) + slot * PB + 4 * sg) = v;
            }
            __syncthreads();
            // ---- mma: 4 k16 steps per chunk, 3-term split ----
#pragma unroll
            for (int ks = 0; ks < 4; ks++) {
                int kq = ks * 8 + qd;
                uint32_t ah[2][4], al[2][4];
#pragma unroll
                for (int mt = 0; mt < 2; mt++) {
                    int pxb = mbase + 16 * mt;
                    ah[mt][0] = AH[kq * PA + pxb + g];
                    ah[mt][1] = AH[kq * PA + pxb + g + 8];
                    ah[mt][2] = AH[(kq + 4) * PA + pxb + g];
                    ah[mt][3] = AH[(kq + 4) * PA + pxb + g + 8];
                    al[mt][0] = AL[kq * PA + pxb + g];
                    al[mt][1] = AL[kq * PA + pxb + g + 8];
                    al[mt][2] = AL[(kq + 4) * PA + pxb + g];
                    al[mt][3] = AL[(kq + 4) * PA + pxb + g + 8];
                }
#pragma unroll
                for (int nt = 0; nt < 8; nt++) {
                    int srow = nbase + 8 * nt + g;
                    uint32_t bh0 = BH[srow * PB + kq];
                    uint32_t bh1 = BH[srow * PB + kq + 4];
                    uint32_t bl0 = BL[srow * PB + kq];
                    uint32_t bl1 = BL[srow * PB + kq + 4];
#pragma unroll
                    for (int mt = 0; mt < 2; mt++) {
                        MMA_F16(acc[mt][nt], ah[mt], bh0, bh1);
                        MMA_F16(acc[mt][nt], ah[mt], bl0, bl1);
                        MMA_F16(acc[mt][nt], al[mt], bh0, bh1);
                    }
                }
            }
            __syncthreads();
        }

        // ---- pass 0: reduce per-px sumsq -> nrm ----
        if (pass == 0) {
            int r0 = t >> 5, seg = t & 31;
            float* part = dsm + OFF_STAT;
            *(float4*)(part + (r0 * 32 + seg) * 4) = ssv;
            __syncthreads();
            if (t < 128) {
                float s = 0.f;
#pragma unroll
                for (int r = 0; r < 8; r++) s += part[(r * 32 + (t >> 2)) * 4 + (t & 3)];
                dsm[OFF_NRM + t] = fmaxf(sqrtf(s), 1e-4f);
            }
            __syncthreads();
        }

        // ---- write d-matrix (overlay A/B region) ----
        float* dbuf = dsm;
#pragma unroll
        for (int mt = 0; mt < 2; mt++) {
            int r0 = mbase + 16 * mt + g;
            int r1 = r0 + 8;
            float sc0 = 20.f / dsm[OFF_NRM + r0];
            float sc1 = 20.f / dsm[OFF_NRM + r1];
#pragma unroll
            for (int nt = 0; nt < 8; nt++) {
                int nloc = nbase + 8 * nt + 2 * qd;
                int ngl = SB + nloc;
                float d0 = (ngl     < S) ? acc[mt][nt][0] * sc0 : NEG;
                float d1 = (ngl + 1 < S) ? acc[mt][nt][1] * sc0 : NEG;
                float d2 = (ngl     < S) ? acc[mt][nt][2] * sc1 : NEG;
                float d3 = (ngl + 1 < S) ? acc[mt][nt][3] * sc1 : NEG;
                *(float2*)(dbuf + r0 * PD + nloc) = make_float2(d0, d1);
                *(float2*)(dbuf + r1 * PD + nloc) = make_float2(d2, d3);
            }
        }
        __syncthreads();

        // ---- epilogue: warp owns px 16*warp..+15 ----
        for (int pi = 0; pi < 16; pi++) {
            int px = warp * 16 + pi;
            const float* dp = dbuf + px * PD;
            float bm = -CUDART_INF_F; int bi = 0;
#pragma unroll
            for (int k = 0; k < 4; k++) {
                int n = k * 32 + lane;
                float v = dp[n];
                if (v > bm) { bm = v; bi = n; }
            }
#pragma unroll
            for (int o = 16; o; o >>= 1) {
                float om = __shfl_xor_sync(0xffffffffu, bm, o);
                int   oi = __shfl_xor_sync(0xffffffffu, bi, o);
                if (om > bm || (om == bm && oi < bi)) { bm = om; bi = oi; }
            }
            float se = 0.f, sd = 0.f;
#pragma unroll
            for (int k = 0; k < 4; k++) {
                float v = dp[k * 32 + lane];
                float e = fast_exp_neg(v - bm);
                se += e; sd += e * v;
            }
            se = warp_sum(se); sd = warp_sum(sd);
            if (lane == 0) {
                if (npass == 1) {
                    if (S == 0) { out[p0 + px] = NEG; out[HW + p0 + px] = 0.f; }
                    else        { out[p0 + px] = sd / se; out[HW + p0 + px] = (float)sidx[bi]; }
                } else if (pass == 0) {
                    stM[px] = bm; stE[px] = se; stD[px] = sd; stB[px] = bi;
                } else {
                    float bm0 = stM[px], se0 = stE[px], sd0 = stD[px];
                    int bi0 = stB[px];
                    int big = 128 + bi;
                    float M = fmaxf(bm0, bm);
                    int bif = (bm > bm0) ? big : bi0;     // pass0 wins ties (lower index)
                    float ra = fast_exp_neg(bm0 - M), rb = fast_exp_neg(bm - M);
                    float seT = se0 * ra + se * rb;
                    float sdT = sd0 * ra + sd * rb;
                    out[p0 + px]      = sdT / seT;
                    out[HW + p0 + px] = (float)sidx[bif];
                }
            }
        }
        __syncthreads();
    }
}

// ---------------- launcher ----------------
extern "C" void kernel_launch(void* const* d_in, const int* in_sizes, int n_in,
                              void* d_out, int out_size) {
    const float* qry   = (const float*)d_in[0];
    const float* sup_x = (const float*)d_in[1];
    const float* sup_y = (const float*)d_in[2];
    const float* cal   = (const float*)d_in[4];
    float* out = (float*)d_out;

    cudaFuncSetAttribute(dist_kernel, cudaFuncAttributeMaxDynamicSharedMemorySize, DIST_SMEM);

    pool_x_kernel<<<256, 256>>>(sup_x);
    pool_y_sel_kernel<<<1, 256>>>(sup_y);
    band_kernel<<<256, 256>>>(cal);
    proto_kernel<<<256, 256>>>();
    dist_kernel<<<HW / PXT, 256, DIST_SMEM>>>(qry, out);
}